// round 4
// baseline (speedup 1.0000x reference)
#include <cuda_runtime.h>
#include <cuda_bf16.h>
#include <math_constants.h>

#define Nn 50000
#define NF 256
#define NH 64
#define NC 40
#define NE 800000
#define NHW 80   // concat of the two 40-wide heads

typedef unsigned long long ull;

// packed f32x2 helpers (FFMA2 path — ptxas won't emit from plain C++)
#define FMA2(acc, a, b) asm("fma.rn.f32x2 %0, %1, %2, %0;" : "+l"(acc) : "l"(a), "l"(b))
#define PACK2(d, lo, hi) asm("mov.b64 %0, {%1, %2};" : "=l"(d) : "f"(lo), "f"(hi))
#define UNPACK2(lo, hi, s) asm("mov.b64 {%0, %1}, %2;" : "=f"(lo), "=f"(hi) : "l"(s))

// -------- device scratch (no allocs allowed) --------
__device__ float g_xw[(size_t)Nn * NH];    // x @ W1
__device__ float g_h[(size_t)Nn * NH];     // spmm1 result (pre-bias/relu)
__device__ float g_hw[(size_t)Nn * NHW];   // relu(h+b1) @ [W11|W12]
__device__ int   g_cnt[Nn];                // per-dst edge counts
__device__ int   g_start[Nn];              // per-dst segment start (unsorted layout)
__device__ int   g_cursor[Nn];             // scatter cursors
__device__ int   g_total;                  // global segment allocator
__device__ int2  g_pedge[NE];              // permuted (src, val-bits) grouped by dst

// ---------------- zero counts + allocator ----------------
__global__ __launch_bounds__(256) void zero_cnt() {
    int i = blockIdx.x * 256 + threadIdx.x;
    if (i < Nn / 4)
        reinterpret_cast<int4*>(g_cnt)[i] = make_int4(0, 0, 0, 0);
    if (i == 0) g_total = 0;
}

// ---------------- histogram of dst (4 edges/thread) ----------------
__global__ __launch_bounds__(256) void hist(const int* __restrict__ dst) {
    int i = blockIdx.x * 256 + threadIdx.x;
    if (i < NE / 4) {
        int4 d = reinterpret_cast<const int4*>(dst)[i];
        atomicAdd(&g_cnt[d.x], 1);
        atomicAdd(&g_cnt[d.y], 1);
        atomicAdd(&g_cnt[d.z], 1);
        atomicAdd(&g_cnt[d.w], 1);
    }
}

// ------- segment assign: disjoint per-row ranges via warp scan + 1 atomic -------
__global__ __launch_bounds__(256) void assign_seg() {
    int i = blockIdx.x * 256 + threadIdx.x;
    int lane = threadIdx.x & 31;
    int c = (i < Nn) ? g_cnt[i] : 0;
    int s = c;
#pragma unroll
    for (int o = 1; o < 32; o <<= 1) {
        int n = __shfl_up_sync(0xFFFFFFFFu, s, o);
        if (lane >= o) s += n;
    }
    int base = 0;
    if (lane == 31) base = atomicAdd(&g_total, s);
    base = __shfl_sync(0xFFFFFFFFu, base, 31);
    int start = base + s - c;
    if (i < Nn) {
        g_start[i] = start;
        g_cursor[i] = start;
    }
}

// ---------------- scatter edges into grouped order (4 edges/thread) ----------------
__global__ __launch_bounds__(256) void scatter(const int* __restrict__ src,
                                               const int* __restrict__ dst,
                                               const float* __restrict__ val) {
    int i = blockIdx.x * 256 + threadIdx.x;
    if (i >= NE / 4) return;
    int4 s = reinterpret_cast<const int4*>(src)[i];
    int4 d = reinterpret_cast<const int4*>(dst)[i];
    float4 v = reinterpret_cast<const float4*>(val)[i];
    int p0 = atomicAdd(&g_cursor[d.x], 1);
    int p1 = atomicAdd(&g_cursor[d.y], 1);
    int p2 = atomicAdd(&g_cursor[d.z], 1);
    int p3 = atomicAdd(&g_cursor[d.w], 1);
    g_pedge[p0] = make_int2(s.x, __float_as_int(v.x));
    g_pedge[p1] = make_int2(s.y, __float_as_int(v.y));
    g_pedge[p2] = make_int2(s.z, __float_as_int(v.z));
    g_pedge[p3] = make_int2(s.w, __float_as_int(v.w));
}

// ---------------- GEMM1: xw = x @ W1  (50000x256 @ 256x64), FFMA2 ----------------
__global__ __launch_bounds__(256) void gemm1(const float* __restrict__ x,
                                             const float* __restrict__ W1) {
    __shared__ __align__(16) float xs[128][32];  // 16KB
    __shared__ __align__(16) float ws[32][64];   // 8KB
    int tid = threadIdx.x;
    int m0 = blockIdx.x * 128;
    int c  = tid & 63;       // output column 0..63
    int tg = tid >> 6;       // row group 0..3

    ull acc2[32];            // (even-k partial, odd-k partial)
#pragma unroll
    for (int i = 0; i < 32; i++) acc2[i] = 0ull;

    for (int k0 = 0; k0 < NF; k0 += 32) {
#pragma unroll
        for (int p = 0; p < 4; p++) {
            int idx = tid + p * 256;
            int r   = idx >> 3;
            int kk  = (idx & 7) << 2;
            int row = m0 + r;
            float4 v = make_float4(0.f, 0.f, 0.f, 0.f);
            if (row < Nn)
                v = *reinterpret_cast<const float4*>(&x[(size_t)row * NF + k0 + kk]);
            *reinterpret_cast<float4*>(&xs[r][kk]) = v;
        }
#pragma unroll
        for (int p = 0; p < 2; p++) {
            int idx = tid + p * 256;
            int kk  = idx >> 4;
            int cc  = (idx & 15) << 2;
            float4 v = *reinterpret_cast<const float4*>(&W1[(size_t)(k0 + kk) * NH + cc]);
            *reinterpret_cast<float4*>(&ws[kk][cc]) = v;
        }
        __syncthreads();
#pragma unroll
        for (int k4 = 0; k4 < 32; k4 += 4) {
            ull w01, w23;
            PACK2(w01, ws[k4 + 0][c], ws[k4 + 1][c]);
            PACK2(w23, ws[k4 + 2][c], ws[k4 + 3][c]);
#pragma unroll
            for (int i = 0; i < 32; i++) {
                const float* xr = &xs[tg * 32 + i][k4];
                ull x01 = *reinterpret_cast<const ull*>(xr);
                ull x23 = *reinterpret_cast<const ull*>(xr + 2);
                FMA2(acc2[i], x01, w01);
                FMA2(acc2[i], x23, w23);
            }
        }
        __syncthreads();
    }
#pragma unroll
    for (int i = 0; i < 32; i++) {
        int row = m0 + tg * 32 + i;
        if (row < Nn) {
            float lo, hi;
            UNPACK2(lo, hi, acc2[i]);
            g_xw[(size_t)row * NH + c] = lo + hi;
        }
    }
}

// ---------------- SpMM1 gather: h[r] = sum_e val*xw[src]  (64 feats) ----------------
__global__ __launch_bounds__(256) void spmm1g() {
    int r = blockIdx.x * 8 + (threadIdx.x >> 5);
    if (r >= Nn) return;
    int lane = threadIdx.x & 31;
    int e0 = g_start[r];
    int e1 = e0 + g_cnt[r];
    ull accA = 0ull, accB = 0ull;
    int e = e0;
    for (; e + 2 <= e1; e += 2) {
        int2 ea = g_pedge[e];
        int2 eb = g_pedge[e + 1];
        ull ta = *reinterpret_cast<const ull*>(&g_xw[(size_t)ea.x * NH + 2 * lane]);
        ull tb = *reinterpret_cast<const ull*>(&g_xw[(size_t)eb.x * NH + 2 * lane]);
        float va = __int_as_float(ea.y);
        float vb = __int_as_float(eb.y);
        ull va2, vb2;
        PACK2(va2, va, va);
        PACK2(vb2, vb, vb);
        FMA2(accA, ta, va2);
        FMA2(accB, tb, vb2);
    }
    if (e < e1) {
        int2 ea = g_pedge[e];
        ull ta = *reinterpret_cast<const ull*>(&g_xw[(size_t)ea.x * NH + 2 * lane]);
        float va = __int_as_float(ea.y);
        ull va2;
        PACK2(va2, va, va);
        FMA2(accA, ta, va2);
    }
    float ax0, ay0, ax1, ay1;
    UNPACK2(ax0, ay0, accA);
    UNPACK2(ax1, ay1, accB);
    reinterpret_cast<float2*>(&g_h[(size_t)r * NH])[lane] =
        make_float2(ax0 + ax1, ay0 + ay1);
}

// ------- GEMM2: hw = relu(h + b1) @ [W11|W12]  (50000x64 @ 64x80), FFMA2 -------
__global__ __launch_bounds__(320) void gemm2(const float* __restrict__ b1,
                                             const float* __restrict__ W11,
                                             const float* __restrict__ W12) {
    __shared__ __align__(16) float hs[32][64];   // 8KB
    __shared__ __align__(16) float wt[80][66];   // transposed weights (20.6KB)
    int tid = threadIdx.x;
    int r0 = blockIdx.x * 128;

    for (int idx = tid; idx < 64 * 80; idx += 320) {
        int k = idx / 80;
        int j = idx % 80;
        wt[j][k] = (j < NC) ? W11[(size_t)k * NC + j] : W12[(size_t)k * NC + (j - NC)];
    }
    int j  = tid % 80;
    int rg = tid / 80;  // 0..3

#pragma unroll
    for (int pass = 0; pass < 4; pass++) {
        int rbase = r0 + pass * 32;
        __syncthreads();
        for (int idx = tid; idx < 32 * 64; idx += 320) {
            int r = idx >> 6;
            int k = idx & 63;
            int row = rbase + r;
            float hv = 0.f;
            if (row < Nn) hv = g_h[(size_t)row * NH + k] + b1[k];
            hs[r][k] = fmaxf(hv, 0.f);
        }
        __syncthreads();

        ull acc2[8];
#pragma unroll
        for (int i = 0; i < 8; i++) acc2[i] = 0ull;
#pragma unroll
        for (int k = 0; k < 64; k += 4) {
            ull w01 = *reinterpret_cast<const ull*>(&wt[j][k]);
            ull w23 = *reinterpret_cast<const ull*>(&wt[j][k + 2]);
#pragma unroll
            for (int i = 0; i < 8; i++) {
                const float* hr = &hs[rg * 8 + i][k];
                ull h01 = *reinterpret_cast<const ull*>(hr);
                ull h23 = *reinterpret_cast<const ull*>(hr + 2);
                FMA2(acc2[i], h01, w01);
                FMA2(acc2[i], h23, w23);
            }
        }
#pragma unroll
        for (int i = 0; i < 8; i++) {
            int row = rbase + rg * 8 + i;
            if (row < Nn) {
                float lo, hi;
                UNPACK2(lo, hi, acc2[i]);
                g_hw[(size_t)row * NHW + j] = lo + hi;
            }
        }
    }
}

// -- SpMM2 gather + finalize: z = eps*exp(logstd)+mean; out = log_softmax(z) --
__global__ __launch_bounds__(256) void spmm2fin(const float* __restrict__ eps,
                                                const float* __restrict__ b11,
                                                const float* __restrict__ b12,
                                                float* __restrict__ out) {
    __shared__ float zrow[8][80];
    int w = threadIdx.x >> 5;
    int lane = threadIdx.x & 31;
    int r = blockIdx.x * 8 + w;
    if (r >= Nn) return;

    int e0 = g_start[r];
    int e1 = e0 + g_cnt[r];
    ull aA = 0ull, aB = 0ull, bA = 0ull, bB = 0ull;
    int e = e0;
    for (; e + 2 <= e1; e += 2) {
        int2 ea = g_pedge[e];
        int2 eb = g_pedge[e + 1];
        const float* ha = &g_hw[(size_t)ea.x * NHW];
        const float* hb = &g_hw[(size_t)eb.x * NHW];
        ull ta = *reinterpret_cast<const ull*>(ha + 2 * lane);
        ull tb = *reinterpret_cast<const ull*>(hb + 2 * lane);
        float va = __int_as_float(ea.y);
        float vb = __int_as_float(eb.y);
        ull va2, vb2;
        PACK2(va2, va, va);
        PACK2(vb2, vb, vb);
        FMA2(aA, ta, va2);
        FMA2(aB, tb, vb2);
        if (lane < 8) {
            ull ua = *reinterpret_cast<const ull*>(ha + 64 + 2 * lane);
            ull ub = *reinterpret_cast<const ull*>(hb + 64 + 2 * lane);
            FMA2(bA, ua, va2);
            FMA2(bB, ub, vb2);
        }
    }
    if (e < e1) {
        int2 ea = g_pedge[e];
        const float* ha = &g_hw[(size_t)ea.x * NHW];
        ull ta = *reinterpret_cast<const ull*>(ha + 2 * lane);
        float va = __int_as_float(ea.y);
        ull va2;
        PACK2(va2, va, va);
        FMA2(aA, ta, va2);
        if (lane < 8) {
            ull ua = *reinterpret_cast<const ull*>(ha + 64 + 2 * lane);
            FMA2(bA, ua, va2);
        }
    }
    {
        float x0, y0, x1, y1;
        UNPACK2(x0, y0, aA);
        UNPACK2(x1, y1, aB);
        zrow[w][lane * 2 + 0] = x0 + x1;
        zrow[w][lane * 2 + 1] = y0 + y1;
        if (lane < 8) {
            UNPACK2(x0, y0, bA);
            UNPACK2(x1, y1, bB);
            zrow[w][64 + lane * 2 + 0] = x0 + x1;
            zrow[w][64 + lane * 2 + 1] = y0 + y1;
        }
    }
    __syncwarp();

    const float* zr = zrow[w];
    float mean0 = zr[lane] + b11[lane];
    float ls0   = zr[NC + lane] + b12[lane];
    float z0 = eps[(size_t)r * NC + lane] * expf(ls0) + mean0;
    float z1 = -CUDART_INF_F;
    if (lane < 8) {
        int jj = 32 + lane;
        float mean1 = zr[jj] + b11[jj];
        float ls1   = zr[NC + jj] + b12[jj];
        z1 = eps[(size_t)r * NC + jj] * expf(ls1) + mean1;
    }
    float mx = fmaxf(z0, z1);
#pragma unroll
    for (int o = 16; o > 0; o >>= 1)
        mx = fmaxf(mx, __shfl_xor_sync(0xFFFFFFFFu, mx, o));
    float sm = expf(z0 - mx) + ((lane < 8) ? expf(z1 - mx) : 0.f);
#pragma unroll
    for (int o = 16; o > 0; o >>= 1)
        sm += __shfl_xor_sync(0xFFFFFFFFu, sm, o);
    float lse = logf(sm) + mx;
    out[(size_t)r * NC + lane] = z0 - lse;
    if (lane < 8)
        out[(size_t)r * NC + 32 + lane] = z1 - lse;
}

extern "C" void kernel_launch(void* const* d_in, const int* in_sizes, int n_in,
                              void* d_out, int out_size) {
    const float* x    = (const float*)d_in[0];
    const int*   esrc = (const int*)d_in[1];
    const int*   edst = (const int*)d_in[2];
    const float* evl  = (const float*)d_in[3];
    const float* eps  = (const float*)d_in[4];
    const float* W1   = (const float*)d_in[5];
    const float* b1   = (const float*)d_in[6];
    const float* W11  = (const float*)d_in[7];
    const float* b11  = (const float*)d_in[8];
    const float* W12  = (const float*)d_in[9];
    const float* b12  = (const float*)d_in[10];
    float* out = (float*)d_out;

    zero_cnt<<<(Nn / 4 + 255) / 256, 256>>>();
    hist<<<(NE / 4 + 255) / 256, 256>>>(edst);
    assign_seg<<<(Nn + 255) / 256, 256>>>();
    scatter<<<(NE / 4 + 255) / 256, 256>>>(esrc, edst, evl);
    gemm1<<<(Nn + 127) / 128, 256>>>(x, W1);
    spmm1g<<<(Nn + 7) / 8, 256>>>();
    gemm2<<<(Nn + 127) / 128, 320>>>(b1, W11, W12);
    spmm2fin<<<(Nn + 7) / 8, 256>>>(eps, b11, b12, out);
}

// round 5
// speedup vs baseline: 1.0723x; 1.0723x over previous
#include <cuda_runtime.h>
#include <cuda_bf16.h>
#include <math_constants.h>

#define Nn 50000
#define NF 256
#define NH 64
#define NC 40
#define NE 800000
#define NHW 80   // concat of the two 40-wide heads

typedef unsigned long long ull;

// packed f32x2 helpers (FFMA2 path — ptxas won't emit from plain C++)
#define FMA2(acc, a, b) asm("fma.rn.f32x2 %0, %1, %2, %0;" : "+l"(acc) : "l"(a), "l"(b))
#define PACK2(d, lo, hi) asm("mov.b64 %0, {%1, %2};" : "=l"(d) : "f"(lo), "f"(hi))
#define UNPACK2(lo, hi, s) asm("mov.b64 {%0, %1}, %2;" : "=f"(lo), "=f"(hi) : "l"(s))

// -------- device scratch (no allocs allowed) --------
__device__ float g_xw[(size_t)Nn * NH];    // x @ W1
__device__ float g_h[(size_t)Nn * NH];     // spmm1 result (pre-bias/relu)
__device__ float g_hw[(size_t)Nn * NHW];   // relu(h+b1) @ [W11|W12]
__device__ int   g_cnt[Nn];                // per-dst edge counts
__device__ int   g_start[Nn];              // per-dst segment start (unsorted layout)
__device__ int   g_cursor[Nn];             // scatter cursors
__device__ int   g_total;                  // global segment allocator
__device__ int2  g_pedge[NE];              // permuted (src, val-bits) grouped by dst

// ---------------- zero counts + allocator ----------------
__global__ __launch_bounds__(256) void zero_cnt() {
    int i = blockIdx.x * 256 + threadIdx.x;
    if (i < Nn) g_cnt[i] = 0;
    if (i == 0) g_total = 0;
}

// ---------------- histogram of dst ----------------
__global__ __launch_bounds__(256) void hist(const int* __restrict__ dst) {
    int e = blockIdx.x * 256 + threadIdx.x;
    if (e < NE) atomicAdd(&g_cnt[dst[e]], 1);
}

// ------- segment assign: disjoint per-row ranges via warp scan + 1 atomic -------
__global__ __launch_bounds__(256) void assign_seg() {
    int i = blockIdx.x * 256 + threadIdx.x;
    int lane = threadIdx.x & 31;
    int c = (i < Nn) ? g_cnt[i] : 0;
    int s = c;
#pragma unroll
    for (int o = 1; o < 32; o <<= 1) {
        int n = __shfl_up_sync(0xFFFFFFFFu, s, o);
        if (lane >= o) s += n;
    }
    int base = 0;
    if (lane == 31) base = atomicAdd(&g_total, s);
    base = __shfl_sync(0xFFFFFFFFu, base, 31);
    int start = base + s - c;
    if (i < Nn) {
        g_start[i] = start;
        g_cursor[i] = start;
    }
}

// ---------------- scatter edges into grouped order ----------------
__global__ __launch_bounds__(256) void scatter(const int* __restrict__ src,
                                               const int* __restrict__ dst,
                                               const float* __restrict__ val) {
    int e = blockIdx.x * 256 + threadIdx.x;
    if (e >= NE) return;
    int d = dst[e];
    int p = atomicAdd(&g_cursor[d], 1);
    g_pedge[p] = make_int2(src[e], __float_as_int(val[e]));
}

// ---- GEMM1: xw = x @ W1  (50000x256 @ 256x64), FFMA2, 16 rows/thread ----
// 512 threads: c = tid&63 (column), tg = tid>>6 (row group of 16).
// acc2[i] = (even-k partial, odd-k partial) — 32 accumulator registers.
__global__ __launch_bounds__(512) void gemm1(const float* __restrict__ x,
                                             const float* __restrict__ W1) {
    __shared__ __align__(16) float xs[128][32];  // 16KB
    __shared__ __align__(16) float ws[32][64];   // 8KB
    int tid = threadIdx.x;
    int m0 = blockIdx.x * 128;
    int c  = tid & 63;       // output column 0..63
    int tg = tid >> 6;       // row group 0..7 (16 rows each)

    ull acc2[16];
#pragma unroll
    for (int i = 0; i < 16; i++) acc2[i] = 0ull;

    for (int k0 = 0; k0 < NF; k0 += 32) {
        // load x tile 128x32 (float4, coalesced): 1024 float4, 2/thread
#pragma unroll
        for (int p = 0; p < 2; p++) {
            int idx = tid + p * 512;
            int r   = idx >> 3;
            int kk  = (idx & 7) << 2;
            int row = m0 + r;
            float4 v = make_float4(0.f, 0.f, 0.f, 0.f);
            if (row < Nn)
                v = *reinterpret_cast<const float4*>(&x[(size_t)row * NF + k0 + kk]);
            *reinterpret_cast<float4*>(&xs[r][kk]) = v;
        }
        // load W tile 32x64 (float4): 512 float4, 1/thread
        {
            int kk = tid >> 4;
            int cc = (tid & 15) << 2;
            float4 v = *reinterpret_cast<const float4*>(&W1[(size_t)kk * NH + k0 * 0 + cc]);
            // note: W1 is [256][64]; row index is k0 + kk
            v = *reinterpret_cast<const float4*>(&W1[(size_t)(k0 + kk) * NH + cc]);
            *reinterpret_cast<float4*>(&ws[kk][cc]) = v;
        }
        __syncthreads();
#pragma unroll
        for (int k4 = 0; k4 < 32; k4 += 4) {
            ull w01, w23;
            PACK2(w01, ws[k4 + 0][c], ws[k4 + 1][c]);
            PACK2(w23, ws[k4 + 2][c], ws[k4 + 3][c]);
#pragma unroll
            for (int i = 0; i < 16; i++) {
                const float* xr = &xs[tg * 16 + i][k4];
                ull x01 = *reinterpret_cast<const ull*>(xr);
                ull x23 = *reinterpret_cast<const ull*>(xr + 2);
                FMA2(acc2[i], x01, w01);
                FMA2(acc2[i], x23, w23);
            }
        }
        __syncthreads();
    }
#pragma unroll
    for (int i = 0; i < 16; i++) {
        int row = m0 + tg * 16 + i;
        if (row < Nn) {
            float lo, hi;
            UNPACK2(lo, hi, acc2[i]);
            g_xw[(size_t)row * NH + c] = lo + hi;
        }
    }
}

// ---------------- SpMM1 gather: h[r] = sum_e val*xw[src]  (64 feats) ----------------
__global__ __launch_bounds__(256) void spmm1g() {
    int r = blockIdx.x * 8 + (threadIdx.x >> 5);
    if (r >= Nn) return;
    int lane = threadIdx.x & 31;
    int e0 = g_start[r], e1 = e0 + g_cnt[r];
    float ax = 0.f, ay = 0.f;
    for (int e = e0; e < e1; e++) {
        int2 ed = g_pedge[e];
        float v = __int_as_float(ed.y);
        float2 t = reinterpret_cast<const float2*>(&g_xw[(size_t)ed.x * NH])[lane];
        ax += v * t.x;
        ay += v * t.y;
    }
    reinterpret_cast<float2*>(&g_h[(size_t)r * NH])[lane] = make_float2(ax, ay);
}

// ------- GEMM2: hw = relu(h + b1) @ [W11|W12]  (50000x64 @ 64x80), FFMA2 -------
__global__ __launch_bounds__(320) void gemm2(const float* __restrict__ b1,
                                             const float* __restrict__ W11,
                                             const float* __restrict__ W12) {
    __shared__ __align__(16) float hs[32][64];   // 8KB
    __shared__ __align__(16) float wt[80][66];   // transposed weights (20.6KB)
    int tid = threadIdx.x;
    int r0 = blockIdx.x * 128;

    for (int idx = tid; idx < 64 * 80; idx += 320) {
        int k = idx / 80;
        int j = idx % 80;
        wt[j][k] = (j < NC) ? W11[(size_t)k * NC + j] : W12[(size_t)k * NC + (j - NC)];
    }
    int j  = tid % 80;
    int rg = tid / 80;  // 0..3

#pragma unroll
    for (int pass = 0; pass < 4; pass++) {
        int rbase = r0 + pass * 32;
        __syncthreads();
        for (int idx = tid; idx < 32 * 64; idx += 320) {
            int r = idx >> 6;
            int k = idx & 63;
            int row = rbase + r;
            float hv = 0.f;
            if (row < Nn) hv = g_h[(size_t)row * NH + k] + b1[k];
            hs[r][k] = fmaxf(hv, 0.f);
        }
        __syncthreads();

        ull acc2[8];
#pragma unroll
        for (int i = 0; i < 8; i++) acc2[i] = 0ull;
#pragma unroll
        for (int k = 0; k < 64; k += 4) {
            ull w01 = *reinterpret_cast<const ull*>(&wt[j][k]);
            ull w23 = *reinterpret_cast<const ull*>(&wt[j][k + 2]);
#pragma unroll
            for (int i = 0; i < 8; i++) {
                const float* hr = &hs[rg * 8 + i][k];
                ull h01 = *reinterpret_cast<const ull*>(hr);
                ull h23 = *reinterpret_cast<const ull*>(hr + 2);
                FMA2(acc2[i], h01, w01);
                FMA2(acc2[i], h23, w23);
            }
        }
#pragma unroll
        for (int i = 0; i < 8; i++) {
            int row = rbase + rg * 8 + i;
            if (row < Nn) {
                float lo, hi;
                UNPACK2(lo, hi, acc2[i]);
                g_hw[(size_t)row * NHW + j] = lo + hi;
            }
        }
    }
}

// -- SpMM2 gather + finalize: z = eps*exp(logstd)+mean; out = log_softmax(z) --
__global__ __launch_bounds__(256) void spmm2fin(const float* __restrict__ eps,
                                                const float* __restrict__ b11,
                                                const float* __restrict__ b12,
                                                float* __restrict__ out) {
    __shared__ float zrow[8][80];
    int w = threadIdx.x >> 5;
    int lane = threadIdx.x & 31;
    int r = blockIdx.x * 8 + w;
    if (r >= Nn) return;

    int e0 = g_start[r], e1 = e0 + g_cnt[r];
    float ax = 0.f, ay = 0.f, bx = 0.f, by = 0.f;
    for (int e = e0; e < e1; e++) {
        int2 ed = g_pedge[e];
        float v = __int_as_float(ed.y);
        const float2* hr = reinterpret_cast<const float2*>(&g_hw[(size_t)ed.x * NHW]);
        float2 t = hr[lane];
        ax += v * t.x;
        ay += v * t.y;
        if (lane < 8) {
            float2 u = hr[32 + lane];
            bx += v * u.x;
            by += v * u.y;
        }
    }
    zrow[w][lane * 2 + 0] = ax;
    zrow[w][lane * 2 + 1] = ay;
    if (lane < 8) {
        zrow[w][64 + lane * 2 + 0] = bx;
        zrow[w][64 + lane * 2 + 1] = by;
    }
    __syncwarp();

    const float* zr = zrow[w];
    float mean0 = zr[lane] + b11[lane];
    float ls0   = zr[NC + lane] + b12[lane];
    float z0 = eps[(size_t)r * NC + lane] * expf(ls0) + mean0;
    float z1 = -CUDART_INF_F;
    if (lane < 8) {
        int jj = 32 + lane;
        float mean1 = zr[jj] + b11[jj];
        float ls1   = zr[NC + jj] + b12[jj];
        z1 = eps[(size_t)r * NC + jj] * expf(ls1) + mean1;
    }
    float mx = fmaxf(z0, z1);
#pragma unroll
    for (int o = 16; o > 0; o >>= 1)
        mx = fmaxf(mx, __shfl_xor_sync(0xFFFFFFFFu, mx, o));
    float sm = expf(z0 - mx) + ((lane < 8) ? expf(z1 - mx) : 0.f);
#pragma unroll
    for (int o = 16; o > 0; o >>= 1)
        sm += __shfl_xor_sync(0xFFFFFFFFu, sm, o);
    float lse = logf(sm) + mx;
    out[(size_t)r * NC + lane] = z0 - lse;
    if (lane < 8)
        out[(size_t)r * NC + 32 + lane] = z1 - lse;
}

extern "C" void kernel_launch(void* const* d_in, const int* in_sizes, int n_in,
                              void* d_out, int out_size) {
    const float* x    = (const float*)d_in[0];
    const int*   esrc = (const int*)d_in[1];
    const int*   edst = (const int*)d_in[2];
    const float* evl  = (const float*)d_in[3];
    const float* eps  = (const float*)d_in[4];
    const float* W1   = (const float*)d_in[5];
    const float* b1   = (const float*)d_in[6];
    const float* W11  = (const float*)d_in[7];
    const float* b11  = (const float*)d_in[8];
    const float* W12  = (const float*)d_in[9];
    const float* b12  = (const float*)d_in[10];
    float* out = (float*)d_out;

    zero_cnt<<<(Nn + 255) / 256, 256>>>();
    hist<<<(NE + 255) / 256, 256>>>(edst);
    assign_seg<<<(Nn + 255) / 256, 256>>>();
    gemm1<<<(Nn + 127) / 128, 512>>>(x, W1);   // 4th launch -> lands in the ncu snapshot
    scatter<<<(NE + 255) / 256, 256>>>(esrc, edst, evl);
    spmm1g<<<(Nn + 7) / 8, 256>>>();
    gemm2<<<(Nn + 127) / 128, 320>>>(b1, W11, W12);
    spmm2fin<<<(Nn + 7) / 8, 256>>>(eps, b11, b12, out);
}

// round 6
// speedup vs baseline: 1.3922x; 1.2983x over previous
#include <cuda_runtime.h>
#include <cuda_bf16.h>
#include <math_constants.h>

#define Nn 50000
#define NF 256
#define NH 64
#define NC 40
#define NE 800000
#define NHW 80   // concat of the two 40-wide heads

typedef unsigned long long ull;

// packed f32x2 helpers (FFMA2 path — ptxas won't emit from plain C++)
#define FMA2(acc, a, b) asm("fma.rn.f32x2 %0, %1, %2, %0;" : "+l"(acc) : "l"(a), "l"(b))
#define PACK2(d, lo, hi) asm("mov.b64 %0, {%1, %2};" : "=l"(d) : "f"(lo), "f"(hi))
#define UNPACK2(lo, hi, s) asm("mov.b64 {%0, %1}, %2;" : "=f"(lo), "=f"(hi) : "l"(s))

// -------- device scratch (no allocs allowed) --------
__device__ float g_xw[(size_t)Nn * NH];    // x @ W1
__device__ float g_h[(size_t)Nn * NH];     // spmm1 result (pre-bias/relu)
__device__ float g_hw[(size_t)Nn * NHW];   // relu(h+b1) @ [W11|W12]
__device__ int   g_cnt[Nn];                // per-dst edge counts
__device__ int   g_start[Nn];              // per-dst segment start (unsorted layout)
__device__ int   g_cursor[Nn];             // scatter cursors
__device__ int   g_total;                  // global segment allocator
__device__ int2  g_pedge[NE];              // permuted (src, val-bits) grouped by dst

// ---------------- zero counts + allocator ----------------
__global__ __launch_bounds__(256) void zero_cnt() {
    int i = blockIdx.x * 256 + threadIdx.x;
    if (i < Nn) g_cnt[i] = 0;
    if (i == 0) g_total = 0;
}

// ---------------- histogram of dst ----------------
__global__ __launch_bounds__(256) void hist(const int* __restrict__ dst) {
    int e = blockIdx.x * 256 + threadIdx.x;
    if (e < NE) atomicAdd(&g_cnt[dst[e]], 1);
}

// ------- segment assign: disjoint per-row ranges via warp scan + 1 atomic -------
__global__ __launch_bounds__(256) void assign_seg() {
    int i = blockIdx.x * 256 + threadIdx.x;
    int lane = threadIdx.x & 31;
    int c = (i < Nn) ? g_cnt[i] : 0;
    int s = c;
#pragma unroll
    for (int o = 1; o < 32; o <<= 1) {
        int n = __shfl_up_sync(0xFFFFFFFFu, s, o);
        if (lane >= o) s += n;
    }
    int base = 0;
    if (lane == 31) base = atomicAdd(&g_total, s);
    base = __shfl_sync(0xFFFFFFFFu, base, 31);
    int start = base + s - c;
    if (i < Nn) {
        g_start[i] = start;
        g_cursor[i] = start;
    }
}

// ---------------- scatter edges into grouped order ----------------
__global__ __launch_bounds__(256) void scatter(const int* __restrict__ src,
                                               const int* __restrict__ dst,
                                               const float* __restrict__ val) {
    int e = blockIdx.x * 256 + threadIdx.x;
    if (e >= NE) return;
    int d = dst[e];
    int p = atomicAdd(&g_cursor[d], 1);
    g_pedge[p] = make_int2(src[e], __float_as_int(val[e]));
}

// ---- GEMM1: xw = x @ W1 (50000x256 @ 256x64) ----
// Register-blocked: 256 threads (16x16), each computes 8 rows x 4 cols.
// x tile stored TRANSPOSED xs_t[k][row] so per-k row-pairs come from LDS.64;
// FFMA2 packs over the M dimension -> 32 accumulator regs for 32 outputs.
#define G1_STR 138   // padded row-stride (even for LDS.64 alignment; 2-way store conflict only)
__global__ __launch_bounds__(256) void gemm1(const float* __restrict__ x,
                                             const float* __restrict__ W1) {
    __shared__ __align__(16) float xs_t[32][G1_STR];  // 17.7KB
    __shared__ __align__(16) float ws[32][64];        // 8KB
    int tid = threadIdx.x;
    int m0 = blockIdx.x * 128;
    int tx = tid & 15;        // col group: c0 = tx*4
    int ty = tid >> 4;        // row group: r0 = ty*8
    int c0 = tx * 4;
    int r0 = ty * 8;

    ull acc2[4][4];           // [row-pair][col]
#pragma unroll
    for (int j = 0; j < 4; j++)
#pragma unroll
        for (int c = 0; c < 4; c++) acc2[j][c] = 0ull;

    for (int k0 = 0; k0 < NF; k0 += 32) {
        // load x tile 128x32 -> transposed into xs_t (4 float4 per thread)
#pragma unroll
        for (int p = 0; p < 4; p++) {
            int idx = tid + p * 256;       // 0..1023
            int r   = idx >> 3;
            int kj  = (idx & 7) << 2;
            int row = m0 + r;
            float4 v = make_float4(0.f, 0.f, 0.f, 0.f);
            if (row < Nn)
                v = *reinterpret_cast<const float4*>(&x[(size_t)row * NF + k0 + kj]);
            xs_t[kj + 0][r] = v.x;
            xs_t[kj + 1][r] = v.y;
            xs_t[kj + 2][r] = v.z;
            xs_t[kj + 3][r] = v.w;
        }
        // load W tile 32x64 (2 float4 per thread)
#pragma unroll
        for (int p = 0; p < 2; p++) {
            int idx = tid + p * 256;       // 0..511
            int kk  = idx >> 4;
            int cc  = (idx & 15) << 2;
            float4 v = *reinterpret_cast<const float4*>(&W1[(size_t)(k0 + kk) * NH + cc]);
            *reinterpret_cast<float4*>(&ws[kk][cc]) = v;
        }
        __syncthreads();
#pragma unroll
        for (int k = 0; k < 32; k++) {
            float4 wv = *reinterpret_cast<const float4*>(&ws[k][c0]);
            ull w0, w1, w2, w3;
            PACK2(w0, wv.x, wv.x);
            PACK2(w1, wv.y, wv.y);
            PACK2(w2, wv.z, wv.z);
            PACK2(w3, wv.w, wv.w);
            const float* xr = &xs_t[k][r0];
            ull a0 = *reinterpret_cast<const ull*>(xr + 0);
            ull a1 = *reinterpret_cast<const ull*>(xr + 2);
            ull a2 = *reinterpret_cast<const ull*>(xr + 4);
            ull a3 = *reinterpret_cast<const ull*>(xr + 6);
            FMA2(acc2[0][0], a0, w0); FMA2(acc2[0][1], a0, w1);
            FMA2(acc2[0][2], a0, w2); FMA2(acc2[0][3], a0, w3);
            FMA2(acc2[1][0], a1, w0); FMA2(acc2[1][1], a1, w1);
            FMA2(acc2[1][2], a1, w2); FMA2(acc2[1][3], a1, w3);
            FMA2(acc2[2][0], a2, w0); FMA2(acc2[2][1], a2, w1);
            FMA2(acc2[2][2], a2, w2); FMA2(acc2[2][3], a2, w3);
            FMA2(acc2[3][0], a3, w0); FMA2(acc2[3][1], a3, w1);
            FMA2(acc2[3][2], a3, w2); FMA2(acc2[3][3], a3, w3);
        }
        __syncthreads();
    }
    // write out: 8 rows x 4 cols per thread
#pragma unroll
    for (int j = 0; j < 4; j++) {
        float e0[4], e1[4];
#pragma unroll
        for (int c = 0; c < 4; c++) UNPACK2(e0[c], e1[c], acc2[j][c]);
        int row = m0 + r0 + 2 * j;
        if (row < Nn)
            *reinterpret_cast<float4*>(&g_xw[(size_t)row * NH + c0]) =
                make_float4(e0[0], e0[1], e0[2], e0[3]);
        if (row + 1 < Nn)
            *reinterpret_cast<float4*>(&g_xw[(size_t)(row + 1) * NH + c0]) =
                make_float4(e1[0], e1[1], e1[2], e1[3]);
    }
}

// ---------------- SpMM1 gather: h[r] = sum_e val*xw[src]  (64 feats) ----------------
__global__ __launch_bounds__(256) void spmm1g() {
    int r = blockIdx.x * 8 + (threadIdx.x >> 5);
    if (r >= Nn) return;
    int lane = threadIdx.x & 31;
    int e0 = g_start[r], e1 = e0 + g_cnt[r];
    float ax = 0.f, ay = 0.f;
    for (int e = e0; e < e1; e++) {
        int2 ed = g_pedge[e];
        float v = __int_as_float(ed.y);
        float2 t = reinterpret_cast<const float2*>(&g_xw[(size_t)ed.x * NH])[lane];
        ax += v * t.x;
        ay += v * t.y;
    }
    reinterpret_cast<float2*>(&g_h[(size_t)r * NH])[lane] = make_float2(ax, ay);
}

// ------- GEMM2: hw = relu(h + b1) @ [W11|W12]  (50000x64 @ 64x80), FFMA2 -------
__global__ __launch_bounds__(320) void gemm2(const float* __restrict__ b1,
                                             const float* __restrict__ W11,
                                             const float* __restrict__ W12) {
    __shared__ __align__(16) float hs[32][64];   // 8KB
    __shared__ __align__(16) float wt[80][66];   // transposed weights (20.6KB)
    int tid = threadIdx.x;
    int r0 = blockIdx.x * 128;

    for (int idx = tid; idx < 64 * 80; idx += 320) {
        int k = idx / 80;
        int j = idx % 80;
        wt[j][k] = (j < NC) ? W11[(size_t)k * NC + j] : W12[(size_t)k * NC + (j - NC)];
    }
    int j  = tid % 80;
    int rg = tid / 80;  // 0..3

#pragma unroll
    for (int pass = 0; pass < 4; pass++) {
        int rbase = r0 + pass * 32;
        __syncthreads();
        for (int idx = tid; idx < 32 * 64; idx += 320) {
            int r = idx >> 6;
            int k = idx & 63;
            int row = rbase + r;
            float hv = 0.f;
            if (row < Nn) hv = g_h[(size_t)row * NH + k] + b1[k];
            hs[r][k] = fmaxf(hv, 0.f);
        }
        __syncthreads();

        ull acc2[8];
#pragma unroll
        for (int i = 0; i < 8; i++) acc2[i] = 0ull;
#pragma unroll
        for (int k = 0; k < 64; k += 4) {
            ull w01 = *reinterpret_cast<const ull*>(&wt[j][k]);
            ull w23 = *reinterpret_cast<const ull*>(&wt[j][k + 2]);
#pragma unroll
            for (int i = 0; i < 8; i++) {
                const float* hr = &hs[rg * 8 + i][k];
                ull h01 = *reinterpret_cast<const ull*>(hr);
                ull h23 = *reinterpret_cast<const ull*>(hr + 2);
                FMA2(acc2[i], h01, w01);
                FMA2(acc2[i], h23, w23);
            }
        }
#pragma unroll
        for (int i = 0; i < 8; i++) {
            int row = rbase + rg * 8 + i;
            if (row < Nn) {
                float lo, hi;
                UNPACK2(lo, hi, acc2[i]);
                g_hw[(size_t)row * NHW + j] = lo + hi;
            }
        }
    }
}

// -- SpMM2 gather + finalize: z = eps*exp(logstd)+mean; out = log_softmax(z) --
__global__ __launch_bounds__(256) void spmm2fin(const float* __restrict__ eps,
                                                const float* __restrict__ b11,
                                                const float* __restrict__ b12,
                                                float* __restrict__ out) {
    __shared__ float zrow[8][80];
    int w = threadIdx.x >> 5;
    int lane = threadIdx.x & 31;
    int r = blockIdx.x * 8 + w;
    if (r >= Nn) return;

    int e0 = g_start[r], e1 = e0 + g_cnt[r];
    float ax = 0.f, ay = 0.f, bx = 0.f, by = 0.f;
    for (int e = e0; e < e1; e++) {
        int2 ed = g_pedge[e];
        float v = __int_as_float(ed.y);
        const float2* hr = reinterpret_cast<const float2*>(&g_hw[(size_t)ed.x * NHW]);
        float2 t = hr[lane];
        ax += v * t.x;
        ay += v * t.y;
        if (lane < 8) {
            float2 u = hr[32 + lane];
            bx += v * u.x;
            by += v * u.y;
        }
    }
    zrow[w][lane * 2 + 0] = ax;
    zrow[w][lane * 2 + 1] = ay;
    if (lane < 8) {
        zrow[w][64 + lane * 2 + 0] = bx;
        zrow[w][64 + lane * 2 + 1] = by;
    }
    __syncwarp();

    const float* zr = zrow[w];
    float mean0 = zr[lane] + b11[lane];
    float ls0   = zr[NC + lane] + b12[lane];
    float z0 = eps[(size_t)r * NC + lane] * expf(ls0) + mean0;
    float z1 = -CUDART_INF_F;
    if (lane < 8) {
        int jj = 32 + lane;
        float mean1 = zr[jj] + b11[jj];
        float ls1   = zr[NC + jj] + b12[jj];
        z1 = eps[(size_t)r * NC + jj] * expf(ls1) + mean1;
    }
    float mx = fmaxf(z0, z1);
#pragma unroll
    for (int o = 16; o > 0; o >>= 1)
        mx = fmaxf(mx, __shfl_xor_sync(0xFFFFFFFFu, mx, o));
    float sm = expf(z0 - mx) + ((lane < 8) ? expf(z1 - mx) : 0.f);
#pragma unroll
    for (int o = 16; o > 0; o >>= 1)
        sm += __shfl_xor_sync(0xFFFFFFFFu, sm, o);
    float lse = logf(sm) + mx;
    out[(size_t)r * NC + lane] = z0 - lse;
    if (lane < 8)
        out[(size_t)r * NC + 32 + lane] = z1 - lse;
}

extern "C" void kernel_launch(void* const* d_in, const int* in_sizes, int n_in,
                              void* d_out, int out_size) {
    const float* x    = (const float*)d_in[0];
    const int*   esrc = (const int*)d_in[1];
    const int*   edst = (const int*)d_in[2];
    const float* evl  = (const float*)d_in[3];
    const float* eps  = (const float*)d_in[4];
    const float* W1   = (const float*)d_in[5];
    const float* b1   = (const float*)d_in[6];
    const float* W11  = (const float*)d_in[7];
    const float* b11  = (const float*)d_in[8];
    const float* W12  = (const float*)d_in[9];
    const float* b12  = (const float*)d_in[10];
    float* out = (float*)d_out;

    zero_cnt<<<(Nn + 255) / 256, 256>>>();
    hist<<<(NE + 255) / 256, 256>>>(edst);
    assign_seg<<<(Nn + 255) / 256, 256>>>();
    gemm1<<<(Nn + 127) / 128, 256>>>(x, W1);   // 4th launch -> lands in the ncu snapshot
    scatter<<<(NE + 255) / 256, 256>>>(esrc, edst, evl);
    spmm1g<<<(Nn + 7) / 8, 256>>>();
    gemm2<<<(Nn + 127) / 128, 320>>>(b1, W11, W12);
    spmm2fin<<<(Nn + 7) / 8, 256>>>(eps, b11, b12, out);
}

// round 9
// speedup vs baseline: 1.4102x; 1.0129x over previous
#include <cuda_runtime.h>
#include <cuda_bf16.h>
#include <math_constants.h>

#define Nn 50000
#define NF 256
#define NH 64
#define NC 40
#define NE 800000
#define NHW 80   // concat of the two 40-wide heads

typedef unsigned long long ull;

// packed f32x2 helpers (FFMA2 path — ptxas won't emit from plain C++)
#define FMA2(acc, a, b) asm("fma.rn.f32x2 %0, %1, %2, %0;" : "+l"(acc) : "l"(a), "l"(b))
#define PACK2(d, lo, hi) asm("mov.b64 %0, {%1, %2};" : "=l"(d) : "f"(lo), "f"(hi))
#define UNPACK2(lo, hi, s) asm("mov.b64 {%0, %1}, %2;" : "=f"(lo), "=f"(hi) : "l"(s))

// -------- device scratch (no allocs allowed) --------
__device__ float g_xw[(size_t)Nn * NH];    // x @ W1
__device__ float g_h[(size_t)Nn * NH];     // spmm1 result (pre-bias/relu)
__device__ float g_hw[(size_t)Nn * NHW];   // relu(h+b1) @ [W11|W12]
__device__ int   g_cnt[Nn];                // per-dst edge counts
__device__ int   g_start[Nn];              // per-dst segment start (unsorted layout)
__device__ int   g_cursor[Nn];             // scatter cursors
__device__ int   g_total;                  // global segment allocator
__device__ int2  g_pedge[NE];              // permuted (src, val-bits) grouped by dst

// ---------------- zero counts + allocator ----------------
__global__ __launch_bounds__(256) void zero_cnt() {
    int i = blockIdx.x * 256 + threadIdx.x;
    if (i < Nn) g_cnt[i] = 0;
    if (i == 0) g_total = 0;
}

// ---------------- histogram of dst ----------------
__global__ __launch_bounds__(256) void hist(const int* __restrict__ dst) {
    int e = blockIdx.x * 256 + threadIdx.x;
    if (e < NE) atomicAdd(&g_cnt[dst[e]], 1);
}

// ------- segment assign: disjoint per-row ranges via warp scan + 1 atomic -------
__global__ __launch_bounds__(256) void assign_seg() {
    int i = blockIdx.x * 256 + threadIdx.x;
    int lane = threadIdx.x & 31;
    int c = (i < Nn) ? g_cnt[i] : 0;
    int s = c;
#pragma unroll
    for (int o = 1; o < 32; o <<= 1) {
        int n = __shfl_up_sync(0xFFFFFFFFu, s, o);
        if (lane >= o) s += n;
    }
    int base = 0;
    if (lane == 31) base = atomicAdd(&g_total, s);
    base = __shfl_sync(0xFFFFFFFFu, base, 31);
    int start = base + s - c;
    if (i < Nn) {
        g_start[i] = start;
        g_cursor[i] = start;
    }
}

// ---------------- scatter edges into grouped order ----------------
__global__ __launch_bounds__(256) void scatter(const int* __restrict__ src,
                                               const int* __restrict__ dst,
                                               const float* __restrict__ val) {
    int e = blockIdx.x * 256 + threadIdx.x;
    if (e >= NE) return;
    int d = dst[e];
    int p = atomicAdd(&g_cursor[d], 1);
    g_pedge[p] = make_int2(src[e], __float_as_int(val[e]));
}

// ---- GEMM1: xw = x @ W1 (50000x256 @ 256x64) ----
// Register-blocked 8x4 microtiles + FFMA2 over M, double-buffered smem with
// register prefetch: LDG(slab i+1) issues before compute(slab i).
#define G1_STR 138
__global__ __launch_bounds__(256) void gemm1(const float* __restrict__ x,
                                             const float* __restrict__ W1) {
    __shared__ __align__(16) float xs_t[2][32][G1_STR];  // 35.3KB
    __shared__ __align__(16) float ws[2][32][64];        // 16KB
    int tid = threadIdx.x;
    int m0 = blockIdx.x * 128;
    int tx = tid & 15;        // col group: c0 = tx*4
    int ty = tid >> 4;        // row group: r0 = ty*8
    int c0 = tx * 4;
    int r0 = ty * 8;

    // per-thread load coordinates
    int xr_[4], xk_[4];
#pragma unroll
    for (int p = 0; p < 4; p++) {
        int idx = tid + p * 256;       // 0..1023 float4 slots of 128x32 tile
        xr_[p] = idx >> 3;
        xk_[p] = (idx & 7) << 2;
    }
    int wk0 = tid >> 4;                // w slot A
    int wc0 = (tid & 15) << 2;
    int wk1 = (tid + 256) >> 4;        // w slot B
    int wc1 = ((tid + 256) & 15) << 2;

    float4 xv[4], wv[2];
    // prologue: load slab 0
#pragma unroll
    for (int p = 0; p < 4; p++) {
        int row = m0 + xr_[p];
        xv[p] = make_float4(0.f, 0.f, 0.f, 0.f);
        if (row < Nn)
            xv[p] = *reinterpret_cast<const float4*>(&x[(size_t)row * NF + xk_[p]]);
    }
    wv[0] = *reinterpret_cast<const float4*>(&W1[(size_t)wk0 * NH + wc0]);
    wv[1] = *reinterpret_cast<const float4*>(&W1[(size_t)wk1 * NH + wc1]);
#pragma unroll
    for (int p = 0; p < 4; p++) {
        xs_t[0][xk_[p] + 0][xr_[p]] = xv[p].x;
        xs_t[0][xk_[p] + 1][xr_[p]] = xv[p].y;
        xs_t[0][xk_[p] + 2][xr_[p]] = xv[p].z;
        xs_t[0][xk_[p] + 3][xr_[p]] = xv[p].w;
    }
    *reinterpret_cast<float4*>(&ws[0][wk0][wc0]) = wv[0];
    *reinterpret_cast<float4*>(&ws[0][wk1][wc1]) = wv[1];
    __syncthreads();

    ull acc2[4][4];
#pragma unroll
    for (int j = 0; j < 4; j++)
#pragma unroll
        for (int c = 0; c < 4; c++) acc2[j][c] = 0ull;

#pragma unroll
    for (int it = 0; it < 8; it++) {
        int b = it & 1;
        int k0n = (it + 1) * 32;
        if (it < 7) {
            // prefetch next slab into registers (latency hidden by compute)
#pragma unroll
            for (int p = 0; p < 4; p++) {
                int row = m0 + xr_[p];
                xv[p] = make_float4(0.f, 0.f, 0.f, 0.f);
                if (row < Nn)
                    xv[p] = *reinterpret_cast<const float4*>(&x[(size_t)row * NF + k0n + xk_[p]]);
            }
            wv[0] = *reinterpret_cast<const float4*>(&W1[(size_t)(k0n + wk0) * NH + wc0]);
            wv[1] = *reinterpret_cast<const float4*>(&W1[(size_t)(k0n + wk1) * NH + wc1]);
        }
#pragma unroll
        for (int k = 0; k < 32; k++) {
            float4 wq = *reinterpret_cast<const float4*>(&ws[b][k][c0]);
            ull w0, w1, w2, w3;
            PACK2(w0, wq.x, wq.x);
            PACK2(w1, wq.y, wq.y);
            PACK2(w2, wq.z, wq.z);
            PACK2(w3, wq.w, wq.w);
            const float* xr = &xs_t[b][k][r0];
            ull a0 = *reinterpret_cast<const ull*>(xr + 0);
            ull a1 = *reinterpret_cast<const ull*>(xr + 2);
            ull a2 = *reinterpret_cast<const ull*>(xr + 4);
            ull a3 = *reinterpret_cast<const ull*>(xr + 6);
            FMA2(acc2[0][0], a0, w0); FMA2(acc2[0][1], a0, w1);
            FMA2(acc2[0][2], a0, w2); FMA2(acc2[0][3], a0, w3);
            FMA2(acc2[1][0], a1, w0); FMA2(acc2[1][1], a1, w1);
            FMA2(acc2[1][2], a1, w2); FMA2(acc2[1][3], a1, w3);
            FMA2(acc2[2][0], a2, w0); FMA2(acc2[2][1], a2, w1);
            FMA2(acc2[2][2], a2, w2); FMA2(acc2[2][3], a2, w3);
            FMA2(acc2[3][0], a3, w0); FMA2(acc2[3][1], a3, w1);
            FMA2(acc2[3][2], a3, w2); FMA2(acc2[3][3], a3, w3);
        }
        if (it < 7) {
            int nb = 1 - b;
#pragma unroll
            for (int p = 0; p < 4; p++) {
                xs_t[nb][xk_[p] + 0][xr_[p]] = xv[p].x;
                xs_t[nb][xk_[p] + 1][xr_[p]] = xv[p].y;
                xs_t[nb][xk_[p] + 2][xr_[p]] = xv[p].z;
                xs_t[nb][xk_[p] + 3][xr_[p]] = xv[p].w;
            }
            *reinterpret_cast<float4*>(&ws[nb][wk0][wc0]) = wv[0];
            *reinterpret_cast<float4*>(&ws[nb][wk1][wc1]) = wv[1];
        }
        __syncthreads();
    }
    // write out: 8 rows x 4 cols per thread
#pragma unroll
    for (int j = 0; j < 4; j++) {
        float e0[4], e1[4];
#pragma unroll
        for (int c = 0; c < 4; c++) UNPACK2(e0[c], e1[c], acc2[j][c]);
        int row = m0 + r0 + 2 * j;
        if (row < Nn)
            *reinterpret_cast<float4*>(&g_xw[(size_t)row * NH + c0]) =
                make_float4(e0[0], e0[1], e0[2], e0[3]);
        if (row + 1 < Nn)
            *reinterpret_cast<float4*>(&g_xw[(size_t)(row + 1) * NH + c0]) =
                make_float4(e1[0], e1[1], e1[2], e1[3]);
    }
}

// ---------------- SpMM1 gather: h[r] = sum_e val*xw[src]  (64 feats) ----------------
__global__ __launch_bounds__(256) void spmm1g() {
    int r = blockIdx.x * 8 + (threadIdx.x >> 5);
    if (r >= Nn) return;
    int lane = threadIdx.x & 31;
    int e0 = g_start[r], e1 = e0 + g_cnt[r];
    float ax = 0.f, ay = 0.f, bx = 0.f, by = 0.f;
    int e = e0;
    for (; e + 2 <= e1; e += 2) {
        int2 ea = g_pedge[e];
        int2 eb = g_pedge[e + 1];
        float2 ta = reinterpret_cast<const float2*>(&g_xw[(size_t)ea.x * NH])[lane];
        float2 tb = reinterpret_cast<const float2*>(&g_xw[(size_t)eb.x * NH])[lane];
        float va = __int_as_float(ea.y);
        float vb = __int_as_float(eb.y);
        ax += va * ta.x; ay += va * ta.y;
        bx += vb * tb.x; by += vb * tb.y;
    }
    if (e < e1) {
        int2 ea = g_pedge[e];
        float2 ta = reinterpret_cast<const float2*>(&g_xw[(size_t)ea.x * NH])[lane];
        float va = __int_as_float(ea.y);
        ax += va * ta.x; ay += va * ta.y;
    }
    reinterpret_cast<float2*>(&g_h[(size_t)r * NH])[lane] =
        make_float2(ax + bx, ay + by);
}

// ------- GEMM2: hw = relu(h + b1) @ [W11|W12]  (50000x64 @ 64x80) -------
// Register-blocked like gemm1: 320 threads, 8 rows x 4 cols each, single K slab.
#define G2_STR 132
__global__ __launch_bounds__(320) void gemm2(const float* __restrict__ b1,
                                             const float* __restrict__ W11,
                                             const float* __restrict__ W12) {
    __shared__ __align__(16) float hs_t[64][G2_STR];  // 33.8KB, [k][row]
    __shared__ __align__(16) float ws2[64][84];       // 21.5KB, [k][j] padded
    __shared__ float b1s[64];
    int tid = threadIdx.x;
    int r0b = blockIdx.x * 128;

    if (tid < 64) b1s[tid] = b1[tid];
    // load weights [k][j]
    for (int idx = tid; idx < 64 * 80; idx += 320) {
        int k = idx / 80;
        int j = idx % 80;
        ws2[k][j] = (j < NC) ? W11[(size_t)k * NC + j] : W12[(size_t)k * NC + (j - NC)];
    }
    __syncthreads();
    // load h slab transposed with bias+relu: 128 rows x 64 k
    for (int idx = tid; idx < 2048; idx += 320) {   // 2048 float4 slots
        int r  = idx >> 4;
        int kj = (idx & 15) << 2;
        int row = r0b + r;
        float4 v = make_float4(0.f, 0.f, 0.f, 0.f);
        if (row < Nn)
            v = *reinterpret_cast<const float4*>(&g_h[(size_t)row * NH + kj]);
        hs_t[kj + 0][r] = fmaxf(v.x + b1s[kj + 0], 0.f);
        hs_t[kj + 1][r] = fmaxf(v.y + b1s[kj + 1], 0.f);
        hs_t[kj + 2][r] = fmaxf(v.z + b1s[kj + 2], 0.f);
        hs_t[kj + 3][r] = fmaxf(v.w + b1s[kj + 3], 0.f);
    }
    __syncthreads();

    int tx = tid % 20;    // col group: c0 = tx*4 (80 cols)
    int ty = tid / 20;    // row group: r0 = ty*8 (128 rows)
    int c0 = tx * 4;
    int r0 = ty * 8;

    ull acc2[4][4];
#pragma unroll
    for (int j = 0; j < 4; j++)
#pragma unroll
        for (int c = 0; c < 4; c++) acc2[j][c] = 0ull;

#pragma unroll
    for (int k = 0; k < 64; k++) {
        float4 wq = *reinterpret_cast<const float4*>(&ws2[k][c0]);
        ull w0, w1, w2, w3;
        PACK2(w0, wq.x, wq.x);
        PACK2(w1, wq.y, wq.y);
        PACK2(w2, wq.z, wq.z);
        PACK2(w3, wq.w, wq.w);
        const float* hr = &hs_t[k][r0];
        ull a0 = *reinterpret_cast<const ull*>(hr + 0);
        ull a1 = *reinterpret_cast<const ull*>(hr + 2);
        ull a2 = *reinterpret_cast<const ull*>(hr + 4);
        ull a3 = *reinterpret_cast<const ull*>(hr + 6);
        FMA2(acc2[0][0], a0, w0); FMA2(acc2[0][1], a0, w1);
        FMA2(acc2[0][2], a0, w2); FMA2(acc2[0][3], a0, w3);
        FMA2(acc2[1][0], a1, w0); FMA2(acc2[1][1], a1, w1);
        FMA2(acc2[1][2], a1, w2); FMA2(acc2[1][3], a1, w3);
        FMA2(acc2[2][0], a2, w0); FMA2(acc2[2][1], a2, w1);
        FMA2(acc2[2][2], a2, w2); FMA2(acc2[2][3], a2, w3);
        FMA2(acc2[3][0], a3, w0); FMA2(acc2[3][1], a3, w1);
        FMA2(acc2[3][2], a3, w2); FMA2(acc2[3][3], a3, w3);
    }
#pragma unroll
    for (int j = 0; j < 4; j++) {
        float e0[4], e1[4];
#pragma unroll
        for (int c = 0; c < 4; c++) UNPACK2(e0[c], e1[c], acc2[j][c]);
        int row = r0b + r0 + 2 * j;
        if (row < Nn)
            *reinterpret_cast<float4*>(&g_hw[(size_t)row * NHW + c0]) =
                make_float4(e0[0], e0[1], e0[2], e0[3]);
        if (row + 1 < Nn)
            *reinterpret_cast<float4*>(&g_hw[(size_t)(row + 1) * NHW + c0]) =
                make_float4(e1[0], e1[1], e1[2], e1[3]);
    }
}

// -- SpMM2 gather + finalize: z = eps*exp(logstd)+mean; out = log_softmax(z) --
__global__ __launch_bounds__(256) void spmm2fin(const float* __restrict__ eps,
                                                const float* __restrict__ b11,
                                                const float* __restrict__ b12,
                                                float* __restrict__ out) {
    __shared__ float zrow[8][80];
    int w = threadIdx.x >> 5;
    int lane = threadIdx.x & 31;
    int r = blockIdx.x * 8 + w;
    if (r >= Nn) return;

    int e0 = g_start[r], e1 = e0 + g_cnt[r];
    float ax = 0.f, ay = 0.f, bx = 0.f, by = 0.f;
    float cx = 0.f, cy = 0.f, dx = 0.f, dy = 0.f;
    int e = e0;
    for (; e + 2 <= e1; e += 2) {
        int2 ea = g_pedge[e];
        int2 eb = g_pedge[e + 1];
        const float2* ha = reinterpret_cast<const float2*>(&g_hw[(size_t)ea.x * NHW]);
        const float2* hb = reinterpret_cast<const float2*>(&g_hw[(size_t)eb.x * NHW]);
        float va = __int_as_float(ea.y);
        float vb = __int_as_float(eb.y);
        float2 ta = ha[lane];
        float2 tb = hb[lane];
        ax += va * ta.x; ay += va * ta.y;
        bx += vb * tb.x; by += vb * tb.y;
        if (lane < 8) {
            float2 ua = ha[32 + lane];
            float2 ub = hb[32 + lane];
            cx += va * ua.x; cy += va * ua.y;
            dx += vb * ub.x; dy += vb * ub.y;
        }
    }
    if (e < e1) {
        int2 ea = g_pedge[e];
        const float2* ha = reinterpret_cast<const float2*>(&g_hw[(size_t)ea.x * NHW]);
        float va = __int_as_float(ea.y);
        float2 ta = ha[lane];
        ax += va * ta.x; ay += va * ta.y;
        if (lane < 8) {
            float2 ua = ha[32 + lane];
            cx += va * ua.x; cy += va * ua.y;
        }
    }
    zrow[w][lane * 2 + 0] = ax + bx;
    zrow[w][lane * 2 + 1] = ay + by;
    if (lane < 8) {
        zrow[w][64 + lane * 2 + 0] = cx + dx;
        zrow[w][64 + lane * 2 + 1] = cy + dy;
    }
    __syncwarp();

    const float* zr = zrow[w];
    float mean0 = zr[lane] + b11[lane];
    float ls0   = zr[NC + lane] + b12[lane];
    float z0 = eps[(size_t)r * NC + lane] * expf(ls0) + mean0;
    float z1 = -CUDART_INF_F;
    if (lane < 8) {
        int jj = 32 + lane;
        float mean1 = zr[jj] + b11[jj];
        float ls1   = zr[NC + jj] + b12[jj];
        z1 = eps[(size_t)r * NC + jj] * expf(ls1) + mean1;
    }
    float mx = fmaxf(z0, z1);
#pragma unroll
    for (int o = 16; o > 0; o >>= 1)
        mx = fmaxf(mx, __shfl_xor_sync(0xFFFFFFFFu, mx, o));
    float sm = expf(z0 - mx) + ((lane < 8) ? expf(z1 - mx) : 0.f);
#pragma unroll
    for (int o = 16; o > 0; o >>= 1)
        sm += __shfl_xor_sync(0xFFFFFFFFu, sm, o);
    float lse = logf(sm) + mx;
    out[(size_t)r * NC + lane] = z0 - lse;
    if (lane < 8)
        out[(size_t)r * NC + 32 + lane] = z1 - lse;
}

extern "C" void kernel_launch(void* const* d_in, const int* in_sizes, int n_in,
                              void* d_out, int out_size) {
    const float* x    = (const float*)d_in[0];
    const int*   esrc = (const int*)d_in[1];
    const int*   edst = (const int*)d_in[2];
    const float* evl  = (const float*)d_in[3];
    const float* eps  = (const float*)d_in[4];
    const float* W1   = (const float*)d_in[5];
    const float* b1   = (const float*)d_in[6];
    const float* W11  = (const float*)d_in[7];
    const float* b11  = (const float*)d_in[8];
    const float* W12  = (const float*)d_in[9];
    const float* b12  = (const float*)d_in[10];
    float* out = (float*)d_out;

    zero_cnt<<<(Nn + 255) / 256, 256>>>();
    hist<<<(NE + 255) / 256, 256>>>(edst);
    assign_seg<<<(Nn + 255) / 256, 256>>>();
    gemm1<<<(Nn + 127) / 128, 256>>>(x, W1);   // 4th launch -> ncu snapshot
    scatter<<<(NE + 255) / 256, 256>>>(esrc, edst, evl);
    spmm1g<<<(Nn + 7) / 8, 256>>>();
    gemm2<<<(Nn + 127) / 128, 320>>>(b1, W11, W12);
    spmm2fin<<<(Nn + 7) / 8, 256>>>(eps, b11, b12, out);
}

// round 10
// speedup vs baseline: 1.4160x; 1.0041x over previous
#include <cuda_runtime.h>
#include <cuda_bf16.h>
#include <math_constants.h>

#define Nn 50000
#define NF 256
#define NH 64
#define NC 40
#define NE 800000

typedef unsigned long long ull;

// packed f32x2 helpers (FFMA2 path — ptxas won't emit from plain C++)
#define FMA2(acc, a, b) asm("fma.rn.f32x2 %0, %1, %2, %0;" : "+l"(acc) : "l"(a), "l"(b))
#define PACK2(d, lo, hi) asm("mov.b64 %0, {%1, %2};" : "=l"(d) : "f"(lo), "f"(hi))
#define UNPACK2(lo, hi, s) asm("mov.b64 {%0, %1}, %2;" : "=f"(lo), "=f"(hi) : "l"(s))

// -------- device scratch (no allocs allowed) --------
__device__ float g_xw[(size_t)Nn * NH];    // x @ W1
__device__ float g_h[(size_t)Nn * NH];     // relu(A·xw + b1)
__device__ float g_t[(size_t)Nn * NH];     // A·g_h
__device__ int   g_cnt[Nn];                // per-dst edge counts
__device__ int   g_start[Nn];              // per-dst segment start (unsorted layout)
__device__ int   g_cursor[Nn];             // scatter cursors
__device__ int   g_total;                  // global segment allocator
__device__ int2  g_pedge[NE];              // permuted (src, val-bits) grouped by dst

// ---------------- zero counts + allocator ----------------
__global__ __launch_bounds__(256) void zero_cnt() {
    int i = blockIdx.x * 256 + threadIdx.x;
    if (i < Nn) g_cnt[i] = 0;
    if (i == 0) g_total = 0;
}

// ---------------- histogram of dst ----------------
__global__ __launch_bounds__(256) void hist(const int* __restrict__ dst) {
    int e = blockIdx.x * 256 + threadIdx.x;
    if (e < NE) atomicAdd(&g_cnt[dst[e]], 1);
}

// ------- segment assign: disjoint per-row ranges via warp scan + 1 atomic -------
__global__ __launch_bounds__(256) void assign_seg() {
    int i = blockIdx.x * 256 + threadIdx.x;
    int lane = threadIdx.x & 31;
    int c = (i < Nn) ? g_cnt[i] : 0;
    int s = c;
#pragma unroll
    for (int o = 1; o < 32; o <<= 1) {
        int n = __shfl_up_sync(0xFFFFFFFFu, s, o);
        if (lane >= o) s += n;
    }
    int base = 0;
    if (lane == 31) base = atomicAdd(&g_total, s);
    base = __shfl_sync(0xFFFFFFFFu, base, 31);
    int start = base + s - c;
    if (i < Nn) {
        g_start[i] = start;
        g_cursor[i] = start;
    }
}

// ---------------- scatter edges into grouped order ----------------
__global__ __launch_bounds__(256) void scatter(const int* __restrict__ src,
                                               const int* __restrict__ dst,
                                               const float* __restrict__ val) {
    int e = blockIdx.x * 256 + threadIdx.x;
    if (e >= NE) return;
    int d = dst[e];
    int p = atomicAdd(&g_cursor[d], 1);
    g_pedge[p] = make_int2(src[e], __float_as_int(val[e]));
}

// ---- GEMM1: xw = x @ W1 (50000x256 @ 256x64) — R6 single-buffer form ----
#define G1_STR 138
__global__ __launch_bounds__(256) void gemm1(const float* __restrict__ x,
                                             const float* __restrict__ W1) {
    __shared__ __align__(16) float xs_t[32][G1_STR];  // 17.7KB
    __shared__ __align__(16) float ws[32][64];        // 8KB
    int tid = threadIdx.x;
    int m0 = blockIdx.x * 128;
    int tx = tid & 15;        // col group: c0 = tx*4
    int ty = tid >> 4;        // row group: r0 = ty*8
    int c0 = tx * 4;
    int r0 = ty * 8;

    ull acc2[4][4];           // [row-pair][col]
#pragma unroll
    for (int j = 0; j < 4; j++)
#pragma unroll
        for (int c = 0; c < 4; c++) acc2[j][c] = 0ull;

    for (int k0 = 0; k0 < NF; k0 += 32) {
#pragma unroll
        for (int p = 0; p < 4; p++) {
            int idx = tid + p * 256;       // 0..1023
            int r   = idx >> 3;
            int kj  = (idx & 7) << 2;
            int row = m0 + r;
            float4 v = make_float4(0.f, 0.f, 0.f, 0.f);
            if (row < Nn)
                v = *reinterpret_cast<const float4*>(&x[(size_t)row * NF + k0 + kj]);
            xs_t[kj + 0][r] = v.x;
            xs_t[kj + 1][r] = v.y;
            xs_t[kj + 2][r] = v.z;
            xs_t[kj + 3][r] = v.w;
        }
#pragma unroll
        for (int p = 0; p < 2; p++) {
            int idx = tid + p * 256;       // 0..511
            int kk  = idx >> 4;
            int cc  = (idx & 15) << 2;
            float4 v = *reinterpret_cast<const float4*>(&W1[(size_t)(k0 + kk) * NH + cc]);
            *reinterpret_cast<float4*>(&ws[kk][cc]) = v;
        }
        __syncthreads();
#pragma unroll
        for (int k = 0; k < 32; k++) {
            float4 wv = *reinterpret_cast<const float4*>(&ws[k][c0]);
            ull w0, w1, w2, w3;
            PACK2(w0, wv.x, wv.x);
            PACK2(w1, wv.y, wv.y);
            PACK2(w2, wv.z, wv.z);
            PACK2(w3, wv.w, wv.w);
            const float* xr = &xs_t[k][r0];
            ull a0 = *reinterpret_cast<const ull*>(xr + 0);
            ull a1 = *reinterpret_cast<const ull*>(xr + 2);
            ull a2 = *reinterpret_cast<const ull*>(xr + 4);
            ull a3 = *reinterpret_cast<const ull*>(xr + 6);
            FMA2(acc2[0][0], a0, w0); FMA2(acc2[0][1], a0, w1);
            FMA2(acc2[0][2], a0, w2); FMA2(acc2[0][3], a0, w3);
            FMA2(acc2[1][0], a1, w0); FMA2(acc2[1][1], a1, w1);
            FMA2(acc2[1][2], a1, w2); FMA2(acc2[1][3], a1, w3);
            FMA2(acc2[2][0], a2, w0); FMA2(acc2[2][1], a2, w1);
            FMA2(acc2[2][2], a2, w2); FMA2(acc2[2][3], a2, w3);
            FMA2(acc2[3][0], a3, w0); FMA2(acc2[3][1], a3, w1);
            FMA2(acc2[3][2], a3, w2); FMA2(acc2[3][3], a3, w3);
        }
        __syncthreads();
    }
#pragma unroll
    for (int j = 0; j < 4; j++) {
        float e0[4], e1[4];
#pragma unroll
        for (int c = 0; c < 4; c++) UNPACK2(e0[c], e1[c], acc2[j][c]);
        int row = m0 + r0 + 2 * j;
        if (row < Nn)
            *reinterpret_cast<float4*>(&g_xw[(size_t)row * NH + c0]) =
                make_float4(e0[0], e0[1], e0[2], e0[3]);
        if (row + 1 < Nn)
            *reinterpret_cast<float4*>(&g_xw[(size_t)(row + 1) * NH + c0]) =
                make_float4(e1[0], e1[1], e1[2], e1[3]);
    }
}

// ---- SpMM1 gather + bias + relu: g_h[r] = relu(sum_e val*xw[src] + b1) ----
__global__ __launch_bounds__(256) void spmm1g(const float* __restrict__ b1) {
    int r = blockIdx.x * 8 + (threadIdx.x >> 5);
    if (r >= Nn) return;
    int lane = threadIdx.x & 31;
    float2 b = reinterpret_cast<const float2*>(b1)[lane];
    int e0 = g_start[r], e1 = e0 + g_cnt[r];
    float ax = 0.f, ay = 0.f, bx = 0.f, by = 0.f;
    int e = e0;
    for (; e + 2 <= e1; e += 2) {
        int2 ea = g_pedge[e];
        int2 eb = g_pedge[e + 1];
        float2 ta = reinterpret_cast<const float2*>(&g_xw[(size_t)ea.x * NH])[lane];
        float2 tb = reinterpret_cast<const float2*>(&g_xw[(size_t)eb.x * NH])[lane];
        float va = __int_as_float(ea.y);
        float vb = __int_as_float(eb.y);
        ax += va * ta.x; ay += va * ta.y;
        bx += vb * tb.x; by += vb * tb.y;
    }
    if (e < e1) {
        int2 ea = g_pedge[e];
        float2 ta = reinterpret_cast<const float2*>(&g_xw[(size_t)ea.x * NH])[lane];
        float va = __int_as_float(ea.y);
        ax += va * ta.x; ay += va * ta.y;
    }
    reinterpret_cast<float2*>(&g_h[(size_t)r * NH])[lane] =
        make_float2(fmaxf(ax + bx + b.x, 0.f), fmaxf(ay + by + b.y, 0.f));
}

// ---- SpMM2 gather: g_t[r] = sum_e val*g_h[src]  (64 feats) ----
__global__ __launch_bounds__(256) void spmm2k() {
    int r = blockIdx.x * 8 + (threadIdx.x >> 5);
    if (r >= Nn) return;
    int lane = threadIdx.x & 31;
    int e0 = g_start[r], e1 = e0 + g_cnt[r];
    float ax = 0.f, ay = 0.f, bx = 0.f, by = 0.f;
    int e = e0;
    for (; e + 2 <= e1; e += 2) {
        int2 ea = g_pedge[e];
        int2 eb = g_pedge[e + 1];
        float2 ta = reinterpret_cast<const float2*>(&g_h[(size_t)ea.x * NH])[lane];
        float2 tb = reinterpret_cast<const float2*>(&g_h[(size_t)eb.x * NH])[lane];
        float va = __int_as_float(ea.y);
        float vb = __int_as_float(eb.y);
        ax += va * ta.x; ay += va * ta.y;
        bx += vb * tb.x; by += vb * tb.y;
    }
    if (e < e1) {
        int2 ea = g_pedge[e];
        float2 ta = reinterpret_cast<const float2*>(&g_h[(size_t)ea.x * NH])[lane];
        float va = __int_as_float(ea.y);
        ax += va * ta.x; ay += va * ta.y;
    }
    reinterpret_cast<float2*>(&g_t[(size_t)r * NH])[lane] =
        make_float2(ax + bx, ay + by);
}

// ---- GEMM2 + finalize: zpre = t @ [W11|W12]; z = eps*exp(zpre_ls+b12)+(zpre_m+b11);
//      out = log_softmax(z).  64 rows/block, 320 threads, FFMA2 microtiles. ----
#define G2_STR 68
__global__ __launch_bounds__(320) void gemm2fin(const float* __restrict__ eps,
                                                const float* __restrict__ W11,
                                                const float* __restrict__ b11,
                                                const float* __restrict__ W12,
                                                const float* __restrict__ b12,
                                                float* __restrict__ out) {
    __shared__ __align__(16) float hs_t[64][G2_STR];  // [k][row], 17.4KB
    __shared__ __align__(16) float ws2[64][84];       // [k][j] padded, 21.5KB
    __shared__ float zs[64][80];                      // z-pre tile, 20KB
    __shared__ float bs[80];                          // b11 | b12
    int tid = threadIdx.x;
    int r0b = blockIdx.x * 64;

    if (tid < 80) bs[tid] = (tid < NC) ? b11[tid] : b12[tid - NC];
    for (int idx = tid; idx < 64 * 80; idx += 320) {
        int k = idx / 80;
        int j = idx % 80;
        ws2[k][j] = (j < NC) ? W11[(size_t)k * NC + j] : W12[(size_t)k * NC + (j - NC)];
    }
    // load t slab transposed: 64 rows x 64 k
    for (int idx = tid; idx < 1024; idx += 320) {
        int r  = idx >> 4;
        int kj = (idx & 15) << 2;
        int row = r0b + r;
        float4 v = make_float4(0.f, 0.f, 0.f, 0.f);
        if (row < Nn)
            v = *reinterpret_cast<const float4*>(&g_t[(size_t)row * NH + kj]);
        hs_t[kj + 0][r] = v.x;
        hs_t[kj + 1][r] = v.y;
        hs_t[kj + 2][r] = v.z;
        hs_t[kj + 3][r] = v.w;
    }
    __syncthreads();

    int tx = tid % 20;    // col group: c0 = 4*tx (80 cols)
    int ty = tid / 20;    // row group: r0 = 4*ty (64 rows)
    int c0 = tx * 4;
    int r0 = ty * 4;

    ull acc2[2][4];
#pragma unroll
    for (int j = 0; j < 2; j++)
#pragma unroll
        for (int c = 0; c < 4; c++) acc2[j][c] = 0ull;

#pragma unroll
    for (int k = 0; k < 64; k++) {
        float4 wq = *reinterpret_cast<const float4*>(&ws2[k][c0]);
        ull w0, w1, w2, w3;
        PACK2(w0, wq.x, wq.x);
        PACK2(w1, wq.y, wq.y);
        PACK2(w2, wq.z, wq.z);
        PACK2(w3, wq.w, wq.w);
        const float* hr = &hs_t[k][r0];
        ull a0 = *reinterpret_cast<const ull*>(hr + 0);
        ull a1 = *reinterpret_cast<const ull*>(hr + 2);
        FMA2(acc2[0][0], a0, w0); FMA2(acc2[0][1], a0, w1);
        FMA2(acc2[0][2], a0, w2); FMA2(acc2[0][3], a0, w3);
        FMA2(acc2[1][0], a1, w0); FMA2(acc2[1][1], a1, w1);
        FMA2(acc2[1][2], a1, w2); FMA2(acc2[1][3], a1, w3);
    }
#pragma unroll
    for (int j = 0; j < 2; j++) {
#pragma unroll
        for (int c = 0; c < 4; c++) {
            float lo, hi;
            UNPACK2(lo, hi, acc2[j][c]);
            zs[r0 + 2 * j][c0 + c]     = lo;
            zs[r0 + 2 * j + 1][c0 + c] = hi;
        }
    }
    __syncthreads();

    // finalize: 10 warps, rows w, w+10, ...
    int w = tid >> 5;
    int lane = tid & 31;
    for (int r = w; r < 64; r += 10) {
        int row = r0b + r;
        if (row >= Nn) continue;
        const float* zr = zs[r];
        float z0 = eps[(size_t)row * NC + lane] * expf(zr[NC + lane] + bs[NC + lane])
                 + zr[lane] + bs[lane];
        float z1 = -CUDART_INF_F;
        if (lane < 8) {
            int jj = 32 + lane;
            z1 = eps[(size_t)row * NC + jj] * expf(zr[NC + jj] + bs[NC + jj])
               + zr[jj] + bs[jj];
        }
        float mx = fmaxf(z0, z1);
#pragma unroll
        for (int o = 16; o > 0; o >>= 1)
            mx = fmaxf(mx, __shfl_xor_sync(0xFFFFFFFFu, mx, o));
        float sm = expf(z0 - mx) + ((lane < 8) ? expf(z1 - mx) : 0.f);
#pragma unroll
        for (int o = 16; o > 0; o >>= 1)
            sm += __shfl_xor_sync(0xFFFFFFFFu, sm, o);
        float lse = logf(sm) + mx;
        out[(size_t)row * NC + lane] = z0 - lse;
        if (lane < 8)
            out[(size_t)row * NC + 32 + lane] = z1 - lse;
    }
}

extern "C" void kernel_launch(void* const* d_in, const int* in_sizes, int n_in,
                              void* d_out, int out_size) {
    const float* x    = (const float*)d_in[0];
    const int*   esrc = (const int*)d_in[1];
    const int*   edst = (const int*)d_in[2];
    const float* evl  = (const float*)d_in[3];
    const float* eps  = (const float*)d_in[4];
    const float* W1   = (const float*)d_in[5];
    const float* b1   = (const float*)d_in[6];
    const float* W11  = (const float*)d_in[7];
    const float* b11  = (const float*)d_in[8];
    const float* W12  = (const float*)d_in[9];
    const float* b12  = (const float*)d_in[10];
    float* out = (float*)d_out;

    zero_cnt<<<(Nn + 255) / 256, 256>>>();
    hist<<<(NE + 255) / 256, 256>>>(edst);
    assign_seg<<<(Nn + 255) / 256, 256>>>();
    gemm1<<<(Nn + 127) / 128, 256>>>(x, W1);   // 4th launch -> ncu snapshot
    scatter<<<(NE + 255) / 256, 256>>>(esrc, edst, evl);
    spmm1g<<<(Nn + 7) / 8, 256>>>(b1);
    spmm2k<<<(Nn + 7) / 8, 256>>>();
    gemm2fin<<<(Nn + 63) / 64, 320>>>(eps, W11, b11, W12, b12, out);
}